// round 5
// baseline (speedup 1.0000x reference)
#include <cuda_runtime.h>
#include <math.h>

#define Bn 2
#define Sn 2048
#define Dn 1024
#define Hn 16
#define DKn 64
#define FDn 64
#define Mrows (Bn*Sn)

// ---------------- scratch ----------------
__device__ float g_Q[Mrows * Dn];
__device__ float g_K[Mrows * Dn];
__device__ float g_V[Mrows * Dn];
__device__ float g_A[Mrows * Dn];
__device__ float g_X[Mrows * Dn];        // x rounded to tf32
__device__ float g_Wr[4][Dn * Dn];       // Wq,Wk,Wv,Wo rounded
__device__ float g_Fn[Bn * Sn * FDn];
__device__ float g_Rn[Bn * Sn * FDn];

__device__ __forceinline__ unsigned f2tf(float x) {
    unsigned r; asm("cvt.rna.tf32.f32 %0, %1;" : "=r"(r) : "f"(x)); return r;
}
__device__ __forceinline__ float ex2(float x) {
    float r; asm("ex2.approx.f32 %0, %1;" : "=f"(r) : "f"(x)); return r;
}
__device__ __forceinline__ void mma8(float* c, unsigned a0, unsigned a1,
                                     unsigned a2, unsigned a3,
                                     unsigned b0, unsigned b1) {
    asm volatile("mma.sync.aligned.m16n8k8.row.col.f32.tf32.tf32.f32 "
                 "{%0,%1,%2,%3}, {%4,%5,%6,%7}, {%8,%9}, {%0,%1,%2,%3};"
                 : "+f"(c[0]), "+f"(c[1]), "+f"(c[2]), "+f"(c[3])
                 : "r"(a0), "r"(a1), "r"(a2), "r"(a3), "r"(b0), "r"(b1));
}
__device__ __forceinline__ void cp16(unsigned dst, const void* src) {
    asm volatile("cp.async.cg.shared.global [%0], [%1], 16;" :: "r"(dst), "l"(src));
}

// ---------------- pre-round x + weights to tf32 ----------------
__global__ __launch_bounds__(256) void round_inputs(
    const float* __restrict__ x,
    const float* __restrict__ Wq, const float* __restrict__ Wk,
    const float* __restrict__ Wv, const float* __restrict__ Wo)
{
    int idx = blockIdx.x * 256 + threadIdx.x;   // float4 index
    const float* s; float* d; int off;
    if (idx < 1048576) { s = x; d = g_X; off = idx; }
    else {
        int j = idx - 1048576;
        int w = j >> 18;  off = j & 262143;
        s = (w == 0) ? Wq : (w == 1) ? Wk : (w == 2) ? Wv : Wo;
        d = g_Wr[w];
    }
    float4 v = ((const float4*)s)[off];
    ((uint4*)d)[off] = make_uint4(f2tf(v.x), f2tf(v.y), f2tf(v.z), f2tf(v.w));
}

// ---------------- l2 normalize (rounded output) ----------------
__global__ __launch_bounds__(256) void l2norm_kernel(
    const float* __restrict__ feat, const float* __restrict__ req,
    float* __restrict__ featn, float* __restrict__ reqn)
{
    int warp = (blockIdx.x * blockDim.x + threadIdx.x) >> 5;
    int lane = threadIdx.x & 31;
    if (warp >= 2 * Bn * Sn) return;
    const float* src; float* dst; int row;
    if (warp < Bn * Sn) { src = feat; dst = featn; row = warp; }
    else                { src = req;  dst = reqn;  row = warp - Bn * Sn; }
    float2 v = ((const float2*)src)[row * 32 + lane];
    float ss = v.x * v.x + v.y * v.y;
    #pragma unroll
    for (int o = 16; o; o >>= 1) ss += __shfl_xor_sync(0xffffffffu, ss, o);
    float inv = 1.0f / fmaxf(sqrtf(ss), 1e-12f);
    ((uint2*)dst)[row * 32 + lane] = make_uint2(f2tf(v.x * inv), f2tf(v.y * inv));
}

// ---------------- tf32 GEMM, cp.async double-buffered ----------------
#define AST 40
#define BST 132
#define STAGE_A (128 * AST)
#define STAGE_B (32 * BST)
#define GSTAGE (STAGE_A + STAGE_B)
#define GEMM_SMEM (2 * GSTAGE * 4)

#define GEMM_CPA(stage, k0) do {                                              \
    unsigned as0 = sbase + (stage) * (GSTAGE * 4);                            \
    unsigned bs0 = as0 + STAGE_A * 4;                                         \
    _Pragma("unroll")                                                         \
    for (int p = 0; p < 4; p++) { int c = tid + 256 * p;                      \
        int r = c >> 3, q = (c & 7) * 4;                                      \
        cp16(as0 + (r * AST + q) * 4, &A[(size_t)(m0 + r) * Dn + (k0) + q]); }\
    _Pragma("unroll")                                                         \
    for (int p = 0; p < 4; p++) { int c = tid + 256 * p;                      \
        int r = c >> 5, q = (c & 31) * 4;                                     \
        cp16(bs0 + (r * BST + q) * 4, &W[(size_t)((k0) + r) * Dn + n0 + q]); }\
    asm volatile("cp.async.commit_group;");                                   \
} while (0)

__global__ __launch_bounds__(256, 2) void gemm_tf32(
    const float* __restrict__ A,
    const float* __restrict__ W0, const float* __restrict__ W1, const float* __restrict__ W2,
    const float* __restrict__ c0p, const float* __restrict__ c1p, const float* __restrict__ c2p,
    float* __restrict__ C0, float* __restrict__ C1, float* __restrict__ C2,
    int roundC)
{
    const float* __restrict__ W    = (blockIdx.z == 0) ? W0 : (blockIdx.z == 1) ? W1 : W2;
    const float* __restrict__ bias = (blockIdx.z == 0) ? c0p : (blockIdx.z == 1) ? c1p : c2p;
    float* __restrict__ C          = (blockIdx.z == 0) ? C0 : (blockIdx.z == 1) ? C1 : C2;

    extern __shared__ unsigned gsm[];
    unsigned sbase = (unsigned)__cvta_generic_to_shared(gsm);

    int tid = threadIdx.x, lane = tid & 31, warp = tid >> 5;
    int g = lane >> 2, t = lane & 3;
    int wm = warp >> 2, wn = warp & 3;
    int m0 = blockIdx.y * 128, n0 = blockIdx.x * 128;

    float acc[4][4][4];
    #pragma unroll
    for (int i = 0; i < 4; i++)
        #pragma unroll
        for (int j = 0; j < 4; j++)
            #pragma unroll
            for (int r = 0; r < 4; r++) acc[i][j][r] = 0.0f;

    GEMM_CPA(0, 0);

    for (int it = 0; it < 32; ++it) {
        int cur = it & 1;
        if (it < 31) {
            GEMM_CPA(cur ^ 1, (it + 1) * 32);
            asm volatile("cp.async.wait_group 1;");
        } else {
            asm volatile("cp.async.wait_group 0;");
        }
        __syncthreads();

        unsigned* Asb = gsm + cur * GSTAGE;
        unsigned* Bsb = Asb + STAGE_A;
        #pragma unroll
        for (int s = 0; s < 4; ++s) {
            int kb = s * 8 + 2 * t;
            unsigned a[4][4];
            #pragma unroll
            for (int mt = 0; mt < 4; ++mt) {
                int r = (wm * 64 + mt * 16 + g) * AST + kb;
                uint2 lo = *(const uint2*)&Asb[r];
                uint2 hi = *(const uint2*)&Asb[r + 8 * AST];
                a[mt][0] = lo.x; a[mt][1] = hi.x; a[mt][2] = lo.y; a[mt][3] = hi.y;
            }
            #pragma unroll
            for (int nt = 0; nt < 4; ++nt) {
                int col = wn * 32 + nt * 8 + g;
                unsigned q0 = Bsb[kb * BST + col];
                unsigned q1 = Bsb[(kb + 1) * BST + col];
                #pragma unroll
                for (int mt = 0; mt < 4; ++mt)
                    mma8(acc[mt][nt], a[mt][0], a[mt][1], a[mt][2], a[mt][3], q0, q1);
            }
        }
        __syncthreads();
    }

    #pragma unroll
    for (int mt = 0; mt < 4; ++mt) {
        int row = m0 + wm * 64 + mt * 16 + g;
        #pragma unroll
        for (int nt = 0; nt < 4; ++nt) {
            int col = n0 + wn * 32 + nt * 8 + 2 * t;
            float b0 = bias[col], b1 = bias[col + 1];
            float x0 = acc[mt][nt][0] + b0, x1 = acc[mt][nt][1] + b1;
            float x2 = acc[mt][nt][2] + b0, x3 = acc[mt][nt][3] + b1;
            if (roundC) {
                x0 = __uint_as_float(f2tf(x0)); x1 = __uint_as_float(f2tf(x1));
                x2 = __uint_as_float(f2tf(x2)); x3 = __uint_as_float(f2tf(x3));
            }
            *(float2*)&C[(size_t)row * Dn + col]       = make_float2(x0, x1);
            *(float2*)&C[(size_t)(row + 8) * Dn + col] = make_float2(x2, x3);
        }
    }
}

// ---------------- tf32 flash attention: 128 threads, q64 x kv32, 2 CTAs/SM ----------------
#define QST 136
#define KST 136
#define VST 68
#define QS_SZ (64 * QST)                  // 8704 u32
#define KS_SZ (32 * KST)                  // 4352
#define VS_SZ (32 * VST)                  // 2176
#define KV_SZ (KS_SZ + VS_SZ)             // 6528
#define ATT_SMEM ((QS_SZ + 2 * KV_SZ) * 4)  // 87040 B -> 2 CTAs/SM

#define ISSUE_KV(stage, kb) do {                                               \
    unsigned ks0 = abase + (QS_SZ + (stage) * KV_SZ) * 4;                      \
    unsigned vs0 = ks0 + KS_SZ * 4;                                            \
    _Pragma("unroll")                                                          \
    for (int p = 0; p < 8; p++) { int c = tid + 128 * p;                       \
        int r = c >> 5, d4 = c & 31;                                           \
        const float* src = (d4 < 16)                                           \
            ? &Kp[(size_t)(rowoff + (kb) + r) * Dn + h * DKn + d4 * 4]         \
            : &Fp[(size_t)(rowoff + (kb) + r) * FDn + (d4 - 16) * 4];          \
        cp16(ks0 + (r * KST + d4 * 4) * 4, src); }                             \
    _Pragma("unroll")                                                          \
    for (int p = 0; p < 4; p++) { int c = tid + 128 * p;                       \
        int r = c >> 4, d4 = c & 15;                                           \
        cp16(vs0 + (r * VST + d4 * 4) * 4,                                     \
             &Vp[(size_t)(rowoff + (kb) + r) * Dn + h * DKn + d4 * 4]); }      \
    asm volatile("cp.async.commit_group;");                                    \
} while (0)

__global__ __launch_bounds__(128) void attn_tf32(
    const float* __restrict__ Qp, const float* __restrict__ Kp, const float* __restrict__ Vp,
    const float* __restrict__ Fp, const float* __restrict__ Rp,
    float* __restrict__ O)
{
    extern __shared__ unsigned sm[];
    unsigned abase = (unsigned)__cvta_generic_to_shared(sm);
    unsigned* Qs = sm;

    int tid = threadIdx.x, lane = tid & 31, warp = tid >> 5;
    int g = lane >> 2, t = lane & 3;
    int qt = 31 - blockIdx.x;                 // biggest tiles first
    int h = blockIdx.y, b = blockIdx.z;
    int qbase = qt * 64, rowoff = b * Sn;
    int wq = warp * 16;

    const float L2E = 1.4426950408889634f;
    // Qext = [log2e/8 * Q | log2e * req_n], tf32
    for (int i = tid; i < 64 * 32; i += 128) {
        int r = i >> 5, d4 = i & 31;
        float4 v; float sc;
        if (d4 < 16) {
            v = *(const float4*)&Qp[(size_t)(rowoff + qbase + r) * Dn + h * DKn + d4 * 4];
            sc = L2E * 0.125f;
        } else {
            v = *(const float4*)&Rp[(size_t)(rowoff + qbase + r) * FDn + (d4 - 16) * 4];
            sc = L2E;
        }
        *(uint4*)&Qs[r * QST + d4 * 4] =
            make_uint4(f2tf(v.x * sc), f2tf(v.y * sc), f2tf(v.z * sc), f2tf(v.w * sc));
    }

    float o[8][4];
    #pragma unroll
    for (int vt = 0; vt < 8; vt++)
        #pragma unroll
        for (int j = 0; j < 4; j++) o[vt][j] = 0.0f;
    float m0 = -1e30f, m1 = -1e30f, l0 = 0.0f, l1 = 0.0f;

    int rg0 = qbase + wq + g, rg1 = rg0 + 8;
    int jmax = 2 * qt + 1;                    // kv tiles of 32

    ISSUE_KV(0, 0);

    for (int jt = 0; jt <= jmax; jt++) {
        int cur = jt & 1;
        if (jt < jmax) {
            ISSUE_KV(cur ^ 1, (jt + 1) * 32);
            asm volatile("cp.async.wait_group 1;");
        } else {
            asm volatile("cp.async.wait_group 0;");
        }
        __syncthreads();

        unsigned* Ks = sm + QS_SZ + cur * KV_SZ;
        unsigned* Vs = Ks + KS_SZ;
        int kb = jt * 32;

        // ---- S = Qext . Kext^T  (16 q-rows x 32 k-cols per warp) ----
        float s[4][4];
        #pragma unroll
        for (int nt = 0; nt < 4; nt++)
            #pragma unroll
            for (int j = 0; j < 4; j++) s[nt][j] = 0.0f;

        #pragma unroll
        for (int oct = 0; oct < 16; oct++) {
            int kk = oct * 8 + 2 * t;
            uint2 alo = *(const uint2*)&Qs[(wq + g) * QST + kk];
            uint2 ahi = *(const uint2*)&Qs[(wq + g + 8) * QST + kk];
            #pragma unroll
            for (int nt = 0; nt < 4; nt++) {
                uint2 bb = *(const uint2*)&Ks[(nt * 8 + g) * KST + kk];
                mma8(s[nt], alo.x, ahi.x, alo.y, ahi.y, bb.x, bb.y);
            }
        }

        // ---- causal mask ----
        if (kb + 31 > rg0) {
            #pragma unroll
            for (int nt = 0; nt < 4; nt++) {
                int c0 = kb + nt * 8 + 2 * t, c1 = c0 + 1;
                if (c0 > rg0) s[nt][0] = -1e30f;
                if (c1 > rg0) s[nt][1] = -1e30f;
                if (c0 > rg1) s[nt][2] = -1e30f;
                if (c1 > rg1) s[nt][3] = -1e30f;
            }
        }

        // ---- online softmax (base-2) ----
        float tm0 = -1e30f, tm1 = -1e30f;
        #pragma unroll
        for (int nt = 0; nt < 4; nt++) {
            tm0 = fmaxf(tm0, fmaxf(s[nt][0], s[nt][1]));
            tm1 = fmaxf(tm1, fmaxf(s[nt][2], s[nt][3]));
        }
        tm0 = fmaxf(tm0, __shfl_xor_sync(0xffffffffu, tm0, 1));
        tm0 = fmaxf(tm0, __shfl_xor_sync(0xffffffffu, tm0, 2));
        tm1 = fmaxf(tm1, __shfl_xor_sync(0xffffffffu, tm1, 1));
        tm1 = fmaxf(tm1, __shfl_xor_sync(0xffffffffu, tm1, 2));
        float mn0 = fmaxf(m0, tm0), mn1 = fmaxf(m1, tm1);
        float cr0 = ex2(m0 - mn0), cr1 = ex2(m1 - mn1);
        float rs0 = 0.0f, rs1 = 0.0f;
        #pragma unroll
        for (int nt = 0; nt < 4; nt++) {
            s[nt][0] = ex2(s[nt][0] - mn0);
            s[nt][1] = ex2(s[nt][1] - mn0);
            s[nt][2] = ex2(s[nt][2] - mn1);
            s[nt][3] = ex2(s[nt][3] - mn1);
            rs0 += s[nt][0] + s[nt][1];
            rs1 += s[nt][2] + s[nt][3];
        }
        rs0 += __shfl_xor_sync(0xffffffffu, rs0, 1);
        rs0 += __shfl_xor_sync(0xffffffffu, rs0, 2);
        rs1 += __shfl_xor_sync(0xffffffffu, rs1, 1);
        rs1 += __shfl_xor_sync(0xffffffffu, rs1, 2);
        l0 = l0 * cr0 + rs0; m0 = mn0;
        l1 = l1 * cr1 + rs1; m1 = mn1;
        #pragma unroll
        for (int vt = 0; vt < 8; vt++) {
            o[vt][0] *= cr0; o[vt][1] *= cr0;
            o[vt][2] *= cr1; o[vt][3] *= cr1;
        }

        // ---- P -> tf32, O += P . V ----
        #pragma unroll
        for (int nt = 0; nt < 4; nt++)
            #pragma unroll
            for (int j = 0; j < 4; j++)
                s[nt][j] = __uint_as_float(f2tf(s[nt][j]));

        #pragma unroll
        for (int oct = 0; oct < 4; oct++) {
            int kk = oct * 8 + 2 * t;
            unsigned pa0 = __float_as_uint(s[oct][0]);
            unsigned pa1 = __float_as_uint(s[oct][2]);
            unsigned pa2 = __float_as_uint(s[oct][1]);
            unsigned pa3 = __float_as_uint(s[oct][3]);
            #pragma unroll
            for (int vt = 0; vt < 8; vt++) {
                unsigned b0 = Vs[kk * VST + vt * 8 + g];
                unsigned b1 = Vs[(kk + 1) * VST + vt * 8 + g];
                mma8(o[vt], pa0, pa1, pa2, pa3, b0, b1);
            }
        }
        __syncthreads();
    }

    // ---- epilogue (rounded: feeds final tf32 GEMM) ----
    float inv0 = 1.0f / l0, inv1 = 1.0f / l1;
    int r0 = rowoff + rg0, r1 = rowoff + rg1;
    #pragma unroll
    for (int vt = 0; vt < 8; vt++) {
        int col = h * DKn + vt * 8 + 2 * t;
        *(uint2*)&O[(size_t)r0 * Dn + col] =
            make_uint2(f2tf(o[vt][0] * inv0), f2tf(o[vt][1] * inv0));
        *(uint2*)&O[(size_t)r1 * Dn + col] =
            make_uint2(f2tf(o[vt][2] * inv1), f2tf(o[vt][3] * inv1));
    }
}

// ---------------- launch ----------------
extern "C" void kernel_launch(void* const* d_in, const int* in_sizes, int n_in,
                              void* d_out, int out_size)
{
    const float* x    = (const float*)d_in[0];
    const float* feat = (const float*)d_in[1];
    const float* req  = (const float*)d_in[2];
    const float* Wq   = (const float*)d_in[3];
    const float* bq   = (const float*)d_in[4];
    const float* Wk   = (const float*)d_in[5];
    const float* bk   = (const float*)d_in[6];
    const float* Wv   = (const float*)d_in[7];
    const float* bv   = (const float*)d_in[8];
    const float* Wo   = (const float*)d_in[9];
    const float* bo   = (const float*)d_in[10];
    float* out = (float*)d_out;

    float *gQ, *gK, *gV, *gA, *gX, *gW, *gFn, *gRn;
    cudaGetSymbolAddress((void**)&gQ,  g_Q);
    cudaGetSymbolAddress((void**)&gK,  g_K);
    cudaGetSymbolAddress((void**)&gV,  g_V);
    cudaGetSymbolAddress((void**)&gA,  g_A);
    cudaGetSymbolAddress((void**)&gX,  g_X);
    cudaGetSymbolAddress((void**)&gW,  g_Wr);
    cudaGetSymbolAddress((void**)&gFn, g_Fn);
    cudaGetSymbolAddress((void**)&gRn, g_Rn);
    const float* gWq = gW;
    const float* gWk = gW + Dn * Dn;
    const float* gWv = gW + 2 * Dn * Dn;
    const float* gWo = gW + 3 * Dn * Dn;

    cudaFuncSetAttribute(gemm_tf32,
                         cudaFuncAttributeMaxDynamicSharedMemorySize, GEMM_SMEM);
    cudaFuncSetAttribute(attn_tf32,
                         cudaFuncAttributeMaxDynamicSharedMemorySize, ATT_SMEM);

    round_inputs<<<8192, 256>>>(x, Wq, Wk, Wv, Wo);
    l2norm_kernel<<<(2 * Bn * Sn) / 8, 256>>>(feat, req, gFn, gRn);

    gemm_tf32<<<dim3(8, 32, 3), 256, GEMM_SMEM>>>(
        gX, gWq, gWk, gWv, bq, bk, bv, gQ, gK, gV, 1);

    attn_tf32<<<dim3(32, Hn, Bn), 128, ATT_SMEM>>>(gQ, gK, gV, gFn, gRn, gA);

    gemm_tf32<<<dim3(8, 32, 1), 256, GEMM_SMEM>>>(
        gA, gWo, gWo, gWo, bo, bo, bo, out, out, out, 0);
}

// round 6
// speedup vs baseline: 1.0508x; 1.0508x over previous
#include <cuda_runtime.h>
#include <math.h>

#define Bn 2
#define Sn 2048
#define Dn 1024
#define Hn 16
#define DKn 64
#define FDn 64
#define Mrows (Bn*Sn)

// ---------------- scratch ----------------
__device__ float g_Q[Mrows * Dn];
__device__ float g_K[Mrows * Dn];
__device__ float g_V[Mrows * Dn];
__device__ float g_A[Mrows * Dn];
__device__ float g_X[Mrows * Dn];        // x rounded to tf32
__device__ float g_Wr[4][Dn * Dn];       // Wq,Wk,Wv,Wo rounded
__device__ float g_Fn[Bn * Sn * FDn];
__device__ float g_Rn[Bn * Sn * FDn];

__device__ __forceinline__ unsigned f2tf(float x) {
    unsigned r; asm("cvt.rna.tf32.f32 %0, %1;" : "=r"(r) : "f"(x)); return r;
}
__device__ __forceinline__ float ex2(float x) {
    float r; asm("ex2.approx.f32 %0, %1;" : "=f"(r) : "f"(x)); return r;
}
__device__ __forceinline__ void mma8(float* c, unsigned a0, unsigned a1,
                                     unsigned a2, unsigned a3,
                                     unsigned b0, unsigned b1) {
    asm volatile("mma.sync.aligned.m16n8k8.row.col.f32.tf32.tf32.f32 "
                 "{%0,%1,%2,%3}, {%4,%5,%6,%7}, {%8,%9}, {%0,%1,%2,%3};"
                 : "+f"(c[0]), "+f"(c[1]), "+f"(c[2]), "+f"(c[3])
                 : "r"(a0), "r"(a1), "r"(a2), "r"(a3), "r"(b0), "r"(b1));
}
__device__ __forceinline__ void cp16(unsigned dst, const void* src) {
    asm volatile("cp.async.cg.shared.global [%0], [%1], 16;" :: "r"(dst), "l"(src));
}

// ---------------- pre-round x + weights to tf32 ----------------
__global__ __launch_bounds__(256) void round_inputs(
    const float* __restrict__ x,
    const float* __restrict__ Wq, const float* __restrict__ Wk,
    const float* __restrict__ Wv, const float* __restrict__ Wo)
{
    int idx = blockIdx.x * 256 + threadIdx.x;   // float4 index
    const float* s; float* d; int off;
    if (idx < 1048576) { s = x; d = g_X; off = idx; }
    else {
        int j = idx - 1048576;
        int w = j >> 18;  off = j & 262143;
        s = (w == 0) ? Wq : (w == 1) ? Wk : (w == 2) ? Wv : Wo;
        d = g_Wr[w];
    }
    float4 v = ((const float4*)s)[off];
    ((uint4*)d)[off] = make_uint4(f2tf(v.x), f2tf(v.y), f2tf(v.z), f2tf(v.w));
}

// ---------------- l2 normalize (rounded output) ----------------
__global__ __launch_bounds__(256) void l2norm_kernel(
    const float* __restrict__ feat, const float* __restrict__ req,
    float* __restrict__ featn, float* __restrict__ reqn)
{
    int warp = (blockIdx.x * blockDim.x + threadIdx.x) >> 5;
    int lane = threadIdx.x & 31;
    if (warp >= 2 * Bn * Sn) return;
    const float* src; float* dst; int row;
    if (warp < Bn * Sn) { src = feat; dst = featn; row = warp; }
    else                { src = req;  dst = reqn;  row = warp - Bn * Sn; }
    float2 v = ((const float2*)src)[row * 32 + lane];
    float ss = v.x * v.x + v.y * v.y;
    #pragma unroll
    for (int o = 16; o; o >>= 1) ss += __shfl_xor_sync(0xffffffffu, ss, o);
    float inv = 1.0f / fmaxf(sqrtf(ss), 1e-12f);
    ((uint2*)dst)[row * 32 + lane] = make_uint2(f2tf(v.x * inv), f2tf(v.y * inv));
}

// ---------------- tf32 GEMM, cp.async double-buffered ----------------
#define AST 40
#define BST 132
#define STAGE_A (128 * AST)
#define STAGE_B (32 * BST)
#define GSTAGE (STAGE_A + STAGE_B)
#define GEMM_SMEM (2 * GSTAGE * 4)

#define GEMM_CPA(stage, k0) do {                                              \
    unsigned as0 = sbase + (stage) * (GSTAGE * 4);                            \
    unsigned bs0 = as0 + STAGE_A * 4;                                         \
    _Pragma("unroll")                                                         \
    for (int p = 0; p < 4; p++) { int c = tid + 256 * p;                      \
        int r = c >> 3, q = (c & 7) * 4;                                      \
        cp16(as0 + (r * AST + q) * 4, &A[(size_t)(m0 + r) * Dn + (k0) + q]); }\
    _Pragma("unroll")                                                         \
    for (int p = 0; p < 4; p++) { int c = tid + 256 * p;                      \
        int r = c >> 5, q = (c & 31) * 4;                                     \
        cp16(bs0 + (r * BST + q) * 4, &W[(size_t)((k0) + r) * Dn + n0 + q]); }\
    asm volatile("cp.async.commit_group;");                                   \
} while (0)

__global__ __launch_bounds__(256, 2) void gemm_tf32(
    const float* __restrict__ A,
    const float* __restrict__ W0, const float* __restrict__ W1, const float* __restrict__ W2,
    const float* __restrict__ c0p, const float* __restrict__ c1p, const float* __restrict__ c2p,
    float* __restrict__ C0, float* __restrict__ C1, float* __restrict__ C2,
    int roundC)
{
    const float* __restrict__ W    = (blockIdx.z == 0) ? W0 : (blockIdx.z == 1) ? W1 : W2;
    const float* __restrict__ bias = (blockIdx.z == 0) ? c0p : (blockIdx.z == 1) ? c1p : c2p;
    float* __restrict__ C          = (blockIdx.z == 0) ? C0 : (blockIdx.z == 1) ? C1 : C2;

    extern __shared__ unsigned gsm[];
    unsigned sbase = (unsigned)__cvta_generic_to_shared(gsm);

    int tid = threadIdx.x, lane = tid & 31, warp = tid >> 5;
    int g = lane >> 2, t = lane & 3;
    int wm = warp >> 2, wn = warp & 3;
    int m0 = blockIdx.y * 128, n0 = blockIdx.x * 128;

    float acc[4][4][4];
    #pragma unroll
    for (int i = 0; i < 4; i++)
        #pragma unroll
        for (int j = 0; j < 4; j++)
            #pragma unroll
            for (int r = 0; r < 4; r++) acc[i][j][r] = 0.0f;

    GEMM_CPA(0, 0);

    for (int it = 0; it < 32; ++it) {
        int cur = it & 1;
        if (it < 31) {
            GEMM_CPA(cur ^ 1, (it + 1) * 32);
            asm volatile("cp.async.wait_group 1;");
        } else {
            asm volatile("cp.async.wait_group 0;");
        }
        __syncthreads();

        unsigned* Asb = gsm + cur * GSTAGE;
        unsigned* Bsb = Asb + STAGE_A;
        #pragma unroll
        for (int s = 0; s < 4; ++s) {
            int kb = s * 8 + 2 * t;
            unsigned a[4][4];
            #pragma unroll
            for (int mt = 0; mt < 4; ++mt) {
                int r = (wm * 64 + mt * 16 + g) * AST + kb;
                uint2 lo = *(const uint2*)&Asb[r];
                uint2 hi = *(const uint2*)&Asb[r + 8 * AST];
                a[mt][0] = lo.x; a[mt][1] = hi.x; a[mt][2] = lo.y; a[mt][3] = hi.y;
            }
            #pragma unroll
            for (int nt = 0; nt < 4; ++nt) {
                int col = wn * 32 + nt * 8 + g;
                unsigned q0 = Bsb[kb * BST + col];
                unsigned q1 = Bsb[(kb + 1) * BST + col];
                #pragma unroll
                for (int mt = 0; mt < 4; ++mt)
                    mma8(acc[mt][nt], a[mt][0], a[mt][1], a[mt][2], a[mt][3], q0, q1);
            }
        }
        __syncthreads();
    }

    #pragma unroll
    for (int mt = 0; mt < 4; ++mt) {
        int row = m0 + wm * 64 + mt * 16 + g;
        #pragma unroll
        for (int nt = 0; nt < 4; ++nt) {
            int col = n0 + wn * 32 + nt * 8 + 2 * t;
            float b0 = bias[col], b1 = bias[col + 1];
            float x0 = acc[mt][nt][0] + b0, x1 = acc[mt][nt][1] + b1;
            float x2 = acc[mt][nt][2] + b0, x3 = acc[mt][nt][3] + b1;
            if (roundC) {
                x0 = __uint_as_float(f2tf(x0)); x1 = __uint_as_float(f2tf(x1));
                x2 = __uint_as_float(f2tf(x2)); x3 = __uint_as_float(f2tf(x3));
            }
            *(float2*)&C[(size_t)row * Dn + col]       = make_float2(x0, x1);
            *(float2*)&C[(size_t)(row + 8) * Dn + col] = make_float2(x2, x3);
        }
    }
}

// ---------------- tf32 flash attention: Q in registers, 3 CTAs/SM ----------------
#define QST 136
#define KST 136
#define VST 68
#define KS_SZ (32 * KST)                  // 4352 u32
#define VS_SZ (32 * VST)                  // 2176
#define KV_SZ (KS_SZ + VS_SZ)             // 6528
#define ATT_SMEM (2 * KV_SZ * 4)          // 52224 B -> 3+ CTAs/SM

#define ISSUE_KV(stage, kb) do {                                               \
    unsigned ks0 = abase + (stage) * (KV_SZ * 4);                              \
    unsigned vs0 = ks0 + KS_SZ * 4;                                            \
    _Pragma("unroll")                                                          \
    for (int p = 0; p < 8; p++) { int c = tid + 128 * p;                       \
        int r = c >> 5, d4 = c & 31;                                           \
        const float* src = (d4 < 16)                                           \
            ? &Kp[(size_t)(rowoff + (kb) + r) * Dn + h * DKn + d4 * 4]         \
            : &Fp[(size_t)(rowoff + (kb) + r) * FDn + (d4 - 16) * 4];          \
        cp16(ks0 + (r * KST + d4 * 4) * 4, src); }                             \
    _Pragma("unroll")                                                          \
    for (int p = 0; p < 4; p++) { int c = tid + 128 * p;                       \
        int r = c >> 4, d4 = c & 15;                                           \
        cp16(vs0 + (r * VST + d4 * 4) * 4,                                     \
             &Vp[(size_t)(rowoff + (kb) + r) * Dn + h * DKn + d4 * 4]); }      \
    asm volatile("cp.async.commit_group;");                                    \
} while (0)

__global__ __launch_bounds__(128, 3) void attn_tf32(
    const float* __restrict__ Qp, const float* __restrict__ Kp, const float* __restrict__ Vp,
    const float* __restrict__ Fp, const float* __restrict__ Rp,
    float* __restrict__ O)
{
    extern __shared__ unsigned sm[];
    unsigned abase = (unsigned)__cvta_generic_to_shared(sm);

    int tid = threadIdx.x, lane = tid & 31, warp = tid >> 5;
    int g = lane >> 2, t = lane & 3;
    int qt = 31 - blockIdx.x;                 // biggest tiles first
    int h = blockIdx.y, b = blockIdx.z;
    int qbase = qt * 64, rowoff = b * Sn;
    int wq = warp * 16;

    const float L2E = 1.4426950408889634f;
    // ---- stage Qext [64][128] into (KV buffer area), then lift to registers ----
    for (int i = tid; i < 64 * 32; i += 128) {
        int r = i >> 5, d4 = i & 31;
        float4 v; float sc;
        if (d4 < 16) {
            v = *(const float4*)&Qp[(size_t)(rowoff + qbase + r) * Dn + h * DKn + d4 * 4];
            sc = L2E * 0.125f;
        } else {
            v = *(const float4*)&Rp[(size_t)(rowoff + qbase + r) * FDn + (d4 - 16) * 4];
            sc = L2E;
        }
        *(uint4*)&sm[r * QST + d4 * 4] =
            make_uint4(f2tf(v.x * sc), f2tf(v.y * sc), f2tf(v.z * sc), f2tf(v.w * sc));
    }
    __syncthreads();

    unsigned qreg[16][4];                      // Q a-fragments: 64 regs
    #pragma unroll
    for (int oct = 0; oct < 16; oct++) {
        int kk = oct * 8 + 2 * t;
        uint2 alo = *(const uint2*)&sm[(wq + g) * QST + kk];
        uint2 ahi = *(const uint2*)&sm[(wq + g + 8) * QST + kk];
        qreg[oct][0] = alo.x; qreg[oct][1] = ahi.x;
        qreg[oct][2] = alo.y; qreg[oct][3] = ahi.y;
    }
    __syncthreads();                           // staging free; KV pipeline may overwrite

    float o[8][4];
    #pragma unroll
    for (int vt = 0; vt < 8; vt++)
        #pragma unroll
        for (int j = 0; j < 4; j++) o[vt][j] = 0.0f;
    float m0 = -1e30f, m1 = -1e30f, l0 = 0.0f, l1 = 0.0f;

    int rg0 = qbase + wq + g, rg1 = rg0 + 8;
    int jmax = 2 * qt + 1;                    // kv tiles of 32

    ISSUE_KV(0, 0);

    for (int jt = 0; jt <= jmax; jt++) {
        int cur = jt & 1;
        if (jt < jmax) {
            ISSUE_KV(cur ^ 1, (jt + 1) * 32);
            asm volatile("cp.async.wait_group 1;");
        } else {
            asm volatile("cp.async.wait_group 0;");
        }
        __syncthreads();

        unsigned* Ks = sm + cur * KV_SZ;
        unsigned* Vs = Ks + KS_SZ;
        int kb = jt * 32;

        // ---- S = Qext . Kext^T  (16 q-rows x 32 k-cols per warp) ----
        float s[4][4];
        #pragma unroll
        for (int nt = 0; nt < 4; nt++)
            #pragma unroll
            for (int j = 0; j < 4; j++) s[nt][j] = 0.0f;

        #pragma unroll
        for (int oct = 0; oct < 16; oct++) {
            int kk = oct * 8 + 2 * t;
            #pragma unroll
            for (int nt = 0; nt < 4; nt++) {
                uint2 bb = *(const uint2*)&Ks[(nt * 8 + g) * KST + kk];
                mma8(s[nt], qreg[oct][0], qreg[oct][1], qreg[oct][2], qreg[oct][3],
                     bb.x, bb.y);
            }
        }

        // ---- causal mask ----
        if (kb + 31 > rg0) {
            #pragma unroll
            for (int nt = 0; nt < 4; nt++) {
                int c0 = kb + nt * 8 + 2 * t, c1 = c0 + 1;
                if (c0 > rg0) s[nt][0] = -1e30f;
                if (c1 > rg0) s[nt][1] = -1e30f;
                if (c0 > rg1) s[nt][2] = -1e30f;
                if (c1 > rg1) s[nt][3] = -1e30f;
            }
        }

        // ---- online softmax (base-2) ----
        float tm0 = -1e30f, tm1 = -1e30f;
        #pragma unroll
        for (int nt = 0; nt < 4; nt++) {
            tm0 = fmaxf(tm0, fmaxf(s[nt][0], s[nt][1]));
            tm1 = fmaxf(tm1, fmaxf(s[nt][2], s[nt][3]));
        }
        tm0 = fmaxf(tm0, __shfl_xor_sync(0xffffffffu, tm0, 1));
        tm0 = fmaxf(tm0, __shfl_xor_sync(0xffffffffu, tm0, 2));
        tm1 = fmaxf(tm1, __shfl_xor_sync(0xffffffffu, tm1, 1));
        tm1 = fmaxf(tm1, __shfl_xor_sync(0xffffffffu, tm1, 2));
        float mn0 = fmaxf(m0, tm0), mn1 = fmaxf(m1, tm1);
        float cr0 = ex2(m0 - mn0), cr1 = ex2(m1 - mn1);
        float rs0 = 0.0f, rs1 = 0.0f;
        #pragma unroll
        for (int nt = 0; nt < 4; nt++) {
            s[nt][0] = ex2(s[nt][0] - mn0);
            s[nt][1] = ex2(s[nt][1] - mn0);
            s[nt][2] = ex2(s[nt][2] - mn1);
            s[nt][3] = ex2(s[nt][3] - mn1);
            rs0 += s[nt][0] + s[nt][1];
            rs1 += s[nt][2] + s[nt][3];
        }
        rs0 += __shfl_xor_sync(0xffffffffu, rs0, 1);
        rs0 += __shfl_xor_sync(0xffffffffu, rs0, 2);
        rs1 += __shfl_xor_sync(0xffffffffu, rs1, 1);
        rs1 += __shfl_xor_sync(0xffffffffu, rs1, 2);
        l0 = l0 * cr0 + rs0; m0 = mn0;
        l1 = l1 * cr1 + rs1; m1 = mn1;
        #pragma unroll
        for (int vt = 0; vt < 8; vt++) {
            o[vt][0] *= cr0; o[vt][1] *= cr0;
            o[vt][2] *= cr1; o[vt][3] *= cr1;
        }

        // ---- P -> tf32, O += P . V ----
        #pragma unroll
        for (int nt = 0; nt < 4; nt++)
            #pragma unroll
            for (int j = 0; j < 4; j++)
                s[nt][j] = __uint_as_float(f2tf(s[nt][j]));

        #pragma unroll
        for (int oct = 0; oct < 4; oct++) {
            int kk = oct * 8 + 2 * t;
            unsigned pa0 = __float_as_uint(s[oct][0]);
            unsigned pa1 = __float_as_uint(s[oct][2]);
            unsigned pa2 = __float_as_uint(s[oct][1]);
            unsigned pa3 = __float_as_uint(s[oct][3]);
            #pragma unroll
            for (int vt = 0; vt < 8; vt++) {
                unsigned b0 = Vs[kk * VST + vt * 8 + g];
                unsigned b1 = Vs[(kk + 1) * VST + vt * 8 + g];
                mma8(o[vt], pa0, pa1, pa2, pa3, b0, b1);
            }
        }
        __syncthreads();
    }

    // ---- epilogue (rounded: feeds final tf32 GEMM) ----
    float inv0 = 1.0f / l0, inv1 = 1.0f / l1;
    int r0 = rowoff + rg0, r1 = rowoff + rg1;
    #pragma unroll
    for (int vt = 0; vt < 8; vt++) {
        int col = h * DKn + vt * 8 + 2 * t;
        *(uint2*)&O[(size_t)r0 * Dn + col] =
            make_uint2(f2tf(o[vt][0] * inv0), f2tf(o[vt][1] * inv0));
        *(uint2*)&O[(size_t)r1 * Dn + col] =
            make_uint2(f2tf(o[vt][2] * inv1), f2tf(o[vt][3] * inv1));
    }
}

// ---------------- launch ----------------
extern "C" void kernel_launch(void* const* d_in, const int* in_sizes, int n_in,
                              void* d_out, int out_size)
{
    const float* x    = (const float*)d_in[0];
    const float* feat = (const float*)d_in[1];
    const float* req  = (const float*)d_in[2];
    const float* Wq   = (const float*)d_in[3];
    const float* bq   = (const float*)d_in[4];
    const float* Wk   = (const float*)d_in[5];
    const float* bk   = (const float*)d_in[6];
    const float* Wv   = (const float*)d_in[7];
    const float* bv   = (const float*)d_in[8];
    const float* Wo   = (const float*)d_in[9];
    const float* bo   = (const float*)d_in[10];
    float* out = (float*)d_out;

    float *gQ, *gK, *gV, *gA, *gX, *gW, *gFn, *gRn;
    cudaGetSymbolAddress((void**)&gQ,  g_Q);
    cudaGetSymbolAddress((void**)&gK,  g_K);
    cudaGetSymbolAddress((void**)&gV,  g_V);
    cudaGetSymbolAddress((void**)&gA,  g_A);
    cudaGetSymbolAddress((void**)&gX,  g_X);
    cudaGetSymbolAddress((void**)&gW,  g_Wr);
    cudaGetSymbolAddress((void**)&gFn, g_Fn);
    cudaGetSymbolAddress((void**)&gRn, g_Rn);
    const float* gWq = gW;
    const float* gWk = gW + Dn * Dn;
    const float* gWv = gW + 2 * Dn * Dn;
    const float* gWo = gW + 3 * Dn * Dn;

    cudaFuncSetAttribute(gemm_tf32,
                         cudaFuncAttributeMaxDynamicSharedMemorySize, GEMM_SMEM);
    cudaFuncSetAttribute(attn_tf32,
                         cudaFuncAttributeMaxDynamicSharedMemorySize, ATT_SMEM);

    round_inputs<<<8192, 256>>>(x, Wq, Wk, Wv, Wo);
    l2norm_kernel<<<(2 * Bn * Sn) / 8, 256>>>(feat, req, gFn, gRn);

    gemm_tf32<<<dim3(8, 32, 3), 256, GEMM_SMEM>>>(
        gX, gWq, gWk, gWv, bq, bk, bv, gQ, gK, gV, 1);

    attn_tf32<<<dim3(32, Hn, Bn), 128, ATT_SMEM>>>(gQ, gK, gV, gFn, gRn, gA);

    gemm_tf32<<<dim3(8, 32, 1), 256, GEMM_SMEM>>>(
        gA, gWo, gWo, gWo, bo, bo, bo, out, out, out, 0);
}

// round 7
// speedup vs baseline: 1.1528x; 1.0971x over previous
#include <cuda_runtime.h>
#include <math.h>

#define Bn 2
#define Sn 2048
#define Dn 1024
#define Hn 16
#define DKn 64
#define FDn 64
#define Mrows (Bn*Sn)

// ---------------- scratch ----------------
__device__ float g_Q[Mrows * Dn];
__device__ float g_K[Mrows * Dn];
__device__ float g_V[Mrows * Dn];
__device__ float g_A[Mrows * Dn];
__device__ float g_X[Mrows * Dn];        // x rounded to tf32
__device__ float g_Wr[4][Dn * Dn];       // Wq,Wk,Wv,Wo rounded
__device__ float g_Fn[Bn * Sn * FDn];
__device__ float g_Rn[Bn * Sn * FDn];
__device__ float g_Bias[(size_t)Bn * Sn * Sn];   // req.feat^T * log2e

__device__ __forceinline__ unsigned f2tf(float x) {
    unsigned r; asm("cvt.rna.tf32.f32 %0, %1;" : "=r"(r) : "f"(x)); return r;
}
__device__ __forceinline__ float ex2(float x) {
    float r; asm("ex2.approx.f32 %0, %1;" : "=f"(r) : "f"(x)); return r;
}
__device__ __forceinline__ void mma8(float* c, unsigned a0, unsigned a1,
                                     unsigned a2, unsigned a3,
                                     unsigned b0, unsigned b1) {
    asm volatile("mma.sync.aligned.m16n8k8.row.col.f32.tf32.tf32.f32 "
                 "{%0,%1,%2,%3}, {%4,%5,%6,%7}, {%8,%9}, {%0,%1,%2,%3};"
                 : "+f"(c[0]), "+f"(c[1]), "+f"(c[2]), "+f"(c[3])
                 : "r"(a0), "r"(a1), "r"(a2), "r"(a3), "r"(b0), "r"(b1));
}
__device__ __forceinline__ void cp16(unsigned dst, const void* src) {
    asm volatile("cp.async.cg.shared.global [%0], [%1], 16;" :: "r"(dst), "l"(src));
}

// ---------------- pre-round x + weights to tf32 ----------------
__global__ __launch_bounds__(256) void round_inputs(
    const float* __restrict__ x,
    const float* __restrict__ Wq, const float* __restrict__ Wk,
    const float* __restrict__ Wv, const float* __restrict__ Wo)
{
    int idx = blockIdx.x * 256 + threadIdx.x;   // float4 index
    const float* s; float* d; int off;
    if (idx < 1048576) { s = x; d = g_X; off = idx; }
    else {
        int j = idx - 1048576;
        int w = j >> 18;  off = j & 262143;
        s = (w == 0) ? Wq : (w == 1) ? Wk : (w == 2) ? Wv : Wo;
        d = g_Wr[w];
    }
    float4 v = ((const float4*)s)[off];
    ((uint4*)d)[off] = make_uint4(f2tf(v.x), f2tf(v.y), f2tf(v.z), f2tf(v.w));
}

// ---------------- l2 normalize (rounded output) ----------------
__global__ __launch_bounds__(256) void l2norm_kernel(
    const float* __restrict__ feat, const float* __restrict__ req,
    float* __restrict__ featn, float* __restrict__ reqn)
{
    int warp = (blockIdx.x * blockDim.x + threadIdx.x) >> 5;
    int lane = threadIdx.x & 31;
    if (warp >= 2 * Bn * Sn) return;
    const float* src; float* dst; int row;
    if (warp < Bn * Sn) { src = feat; dst = featn; row = warp; }
    else                { src = req;  dst = reqn;  row = warp - Bn * Sn; }
    float2 v = ((const float2*)src)[row * 32 + lane];
    float ss = v.x * v.x + v.y * v.y;
    #pragma unroll
    for (int o = 16; o; o >>= 1) ss += __shfl_xor_sync(0xffffffffu, ss, o);
    float inv = 1.0f / fmaxf(sqrtf(ss), 1e-12f);
    ((uint2*)dst)[row * 32 + lane] = make_uint2(f2tf(v.x * inv), f2tf(v.y * inv));
}

// ---------------- bias GEMM: Bias[b] = (Rn . Fn^T) * log2e, lower-tri tiles ----------------
#define FST 72
#define BIAS_SMEM (2 * 128 * FST * 4)   // 73728 B
__global__ __launch_bounds__(256) void bias_gemm(
    const float* __restrict__ Rn, const float* __restrict__ Fn, float* __restrict__ Bias)
{
    if (blockIdx.x > blockIdx.y) return;    // strictly-upper tiles never read
    extern __shared__ unsigned bsm[];
    unsigned* As = bsm;                      // [128][FST] q rows
    unsigned* Bs = bsm + 128 * FST;          // [128][FST] kv rows

    int tid = threadIdx.x, lane = tid & 31, warp = tid >> 5;
    int g = lane >> 2, t = lane & 3;
    int wm = warp >> 2, wn = warp & 3;
    int i0 = blockIdx.y * 128, j0 = blockIdx.x * 128, bz = blockIdx.z;
    const float* R = Rn + (size_t)bz * Sn * FDn;
    const float* F = Fn + (size_t)bz * Sn * FDn;

    for (int i = tid; i < 128 * 16; i += 256) {
        int r = i >> 4, d4 = (i & 15) * 4;
        *(float4*)((float*)&As[r * FST + d4]) = *(const float4*)&R[(size_t)(i0 + r) * FDn + d4];
        *(float4*)((float*)&Bs[r * FST + d4]) = *(const float4*)&F[(size_t)(j0 + r) * FDn + d4];
    }
    __syncthreads();

    float acc[4][4][4];
    #pragma unroll
    for (int i = 0; i < 4; i++)
        #pragma unroll
        for (int j = 0; j < 4; j++)
            #pragma unroll
            for (int r = 0; r < 4; r++) acc[i][j][r] = 0.0f;

    #pragma unroll
    for (int oct = 0; oct < 8; oct++) {
        int kk = oct * 8 + 2 * t;
        #pragma unroll
        for (int mt = 0; mt < 4; mt++) {
            int r = (wm * 64 + mt * 16 + g) * FST + kk;
            uint2 lo = *(const uint2*)&As[r];
            uint2 hi = *(const uint2*)&As[r + 8 * FST];
            #pragma unroll
            for (int nt = 0; nt < 4; nt++) {
                uint2 bb = *(const uint2*)&Bs[(wn * 32 + nt * 8 + g) * FST + kk];
                mma8(acc[mt][nt], lo.x, hi.x, lo.y, hi.y, bb.x, bb.y);
            }
        }
    }

    const float L2E = 1.4426950408889634f;
    float* C = Bias + (size_t)bz * Sn * Sn;
    #pragma unroll
    for (int mt = 0; mt < 4; mt++) {
        int row = i0 + wm * 64 + mt * 16 + g;
        #pragma unroll
        for (int nt = 0; nt < 4; nt++) {
            int col = j0 + wn * 32 + nt * 8 + 2 * t;
            *(float2*)&C[(size_t)row * Sn + col] =
                make_float2(acc[mt][nt][0] * L2E, acc[mt][nt][1] * L2E);
            *(float2*)&C[(size_t)(row + 8) * Sn + col] =
                make_float2(acc[mt][nt][2] * L2E, acc[mt][nt][3] * L2E);
        }
    }
}

// ---------------- tf32 GEMM, cp.async 3-stage pipelined ----------------
#define AST 40
#define BST 132
#define STAGE_A (128 * AST)
#define STAGE_B (32 * BST)
#define GSTAGE (STAGE_A + STAGE_B)
#define GEMM_SMEM (3 * GSTAGE * 4)        // 112128 B

#define GEMM_CPA(stage, k0) do {                                              \
    unsigned as0 = sbase + (stage) * (GSTAGE * 4);                            \
    unsigned bs0 = as0 + STAGE_A * 4;                                         \
    _Pragma("unroll")                                                         \
    for (int p = 0; p < 4; p++) { int c = tid + 256 * p;                      \
        int r = c >> 3, q = (c & 7) * 4;                                      \
        cp16(as0 + (r * AST + q) * 4, &A[(size_t)(m0 + r) * Dn + (k0) + q]); }\
    _Pragma("unroll")                                                         \
    for (int p = 0; p < 4; p++) { int c = tid + 256 * p;                      \
        int r = c >> 5, q = (c & 31) * 4;                                     \
        cp16(bs0 + (r * BST + q) * 4, &W[(size_t)((k0) + r) * Dn + n0 + q]); }\
    asm volatile("cp.async.commit_group;");                                   \
} while (0)

__global__ __launch_bounds__(256, 2) void gemm_tf32(
    const float* __restrict__ A,
    const float* __restrict__ W0, const float* __restrict__ W1, const float* __restrict__ W2,
    const float* __restrict__ c0p, const float* __restrict__ c1p, const float* __restrict__ c2p,
    float* __restrict__ C0, float* __restrict__ C1, float* __restrict__ C2,
    int roundC)
{
    const float* __restrict__ W    = (blockIdx.z == 0) ? W0 : (blockIdx.z == 1) ? W1 : W2;
    const float* __restrict__ bias = (blockIdx.z == 0) ? c0p : (blockIdx.z == 1) ? c1p : c2p;
    float* __restrict__ C          = (blockIdx.z == 0) ? C0 : (blockIdx.z == 1) ? C1 : C2;

    extern __shared__ unsigned gsm[];
    unsigned sbase = (unsigned)__cvta_generic_to_shared(gsm);

    int tid = threadIdx.x, lane = tid & 31, warp = tid >> 5;
    int g = lane >> 2, t = lane & 3;
    int wm = warp >> 2, wn = warp & 3;
    int m0 = blockIdx.y * 128, n0 = blockIdx.x * 128;

    float acc[4][4][4];
    #pragma unroll
    for (int i = 0; i < 4; i++)
        #pragma unroll
        for (int j = 0; j < 4; j++)
            #pragma unroll
            for (int r = 0; r < 4; r++) acc[i][j][r] = 0.0f;

    GEMM_CPA(0, 0);
    GEMM_CPA(1, 32);

    for (int it = 0; it < 32; ++it) {
        if (it < 31) asm volatile("cp.async.wait_group 1;");
        else         asm volatile("cp.async.wait_group 0;");
        __syncthreads();
        if (it < 30) {
            int nst = (it + 2) % 3;
            GEMM_CPA(nst, (it + 2) * 32);
        }
        unsigned* Asb = gsm + (it % 3) * GSTAGE;
        unsigned* Bsb = Asb + STAGE_A;
        #pragma unroll
        for (int s = 0; s < 4; ++s) {
            int kb = s * 8 + 2 * t;
            unsigned a[4][4];
            #pragma unroll
            for (int mt = 0; mt < 4; ++mt) {
                int r = (wm * 64 + mt * 16 + g) * AST + kb;
                uint2 lo = *(const uint2*)&Asb[r];
                uint2 hi = *(const uint2*)&Asb[r + 8 * AST];
                a[mt][0] = lo.x; a[mt][1] = hi.x; a[mt][2] = lo.y; a[mt][3] = hi.y;
            }
            #pragma unroll
            for (int nt = 0; nt < 4; ++nt) {
                int col = wn * 32 + nt * 8 + g;
                unsigned q0 = Bsb[kb * BST + col];
                unsigned q1 = Bsb[(kb + 1) * BST + col];
                #pragma unroll
                for (int mt = 0; mt < 4; ++mt)
                    mma8(acc[mt][nt], a[mt][0], a[mt][1], a[mt][2], a[mt][3], q0, q1);
            }
        }
    }

    #pragma unroll
    for (int mt = 0; mt < 4; ++mt) {
        int row = m0 + wm * 64 + mt * 16 + g;
        #pragma unroll
        for (int nt = 0; nt < 4; ++nt) {
            int col = n0 + wn * 32 + nt * 8 + 2 * t;
            float b0 = bias[col], b1 = bias[col + 1];
            float x0 = acc[mt][nt][0] + b0, x1 = acc[mt][nt][1] + b1;
            float x2 = acc[mt][nt][2] + b0, x3 = acc[mt][nt][3] + b1;
            if (roundC) {
                x0 = __uint_as_float(f2tf(x0)); x1 = __uint_as_float(f2tf(x1));
                x2 = __uint_as_float(f2tf(x2)); x3 = __uint_as_float(f2tf(x3));
            }
            *(float2*)&C[(size_t)row * Dn + col]       = make_float2(x0, x1);
            *(float2*)&C[(size_t)(row + 8) * Dn + col] = make_float2(x2, x3);
        }
    }
}

// ---------------- tf32 flash attention: k=64 S-GEMM + precomputed bias ----------------
#define KST2 72
#define VST2 68
#define BST2 40
#define KS2 (32 * KST2)                   // 2304 u32
#define VS2 (32 * VST2)                   // 2176
#define BS2 (64 * BST2)                   // 2560
#define KVB (KS2 + VS2 + BS2)             // 7040
#define ATT_SMEM (2 * KVB * 4)            // 56320 B -> 4 CTAs/SM

#define ISSUE_KV(stage, kb) do {                                               \
    unsigned ks0 = abase + (stage) * (KVB * 4);                                \
    unsigned vs0 = ks0 + KS2 * 4;                                              \
    unsigned bs0 = vs0 + VS2 * 4;                                              \
    _Pragma("unroll")                                                          \
    for (int p = 0; p < 4; p++) { int c = tid + 128 * p;                       \
        int r = c >> 4, d4 = (c & 15) * 4;                                     \
        cp16(ks0 + (r * KST2 + d4) * 4,                                        \
             &Kp[(size_t)(rowoff + (kb) + r) * Dn + h * DKn + d4]); }          \
    _Pragma("unroll")                                                          \
    for (int p = 0; p < 4; p++) { int c = tid + 128 * p;                       \
        int r = c >> 4, d4 = (c & 15) * 4;                                     \
        cp16(vs0 + (r * VST2 + d4) * 4,                                        \
             &Vp[(size_t)(rowoff + (kb) + r) * Dn + h * DKn + d4]); }          \
    _Pragma("unroll")                                                          \
    for (int p = 0; p < 4; p++) { int c = tid + 128 * p;                       \
        int r = c >> 3, d4 = (c & 7) * 4;                                      \
        cp16(bs0 + (r * BST2 + d4) * 4,                                        \
             &Bbp[(size_t)(qbase + r) * Sn + (kb) + d4]); }                    \
    asm volatile("cp.async.commit_group;");                                    \
} while (0)

__global__ __launch_bounds__(128, 4) void attn_tf32(
    const float* __restrict__ Qp, const float* __restrict__ Kp, const float* __restrict__ Vp,
    const float* __restrict__ Biasp,
    float* __restrict__ O)
{
    extern __shared__ unsigned sm[];
    unsigned abase = (unsigned)__cvta_generic_to_shared(sm);

    int tid = threadIdx.x, lane = tid & 31, warp = tid >> 5;
    int g = lane >> 2, t = lane & 3;
    int qt = 31 - blockIdx.x;                 // biggest tiles first
    int h = blockIdx.y, b = blockIdx.z;
    int qbase = qt * 64, rowoff = b * Sn;
    int wq = warp * 16;
    const float* Bbp = Biasp + (size_t)b * Sn * Sn;

    const float L2E = 1.4426950408889634f;
    // ---- stage Q [64][64] (scaled log2e/8, tf32) then lift to registers ----
    for (int i = tid; i < 64 * 16; i += 128) {
        int r = i >> 4, d4 = (i & 15) * 4;
        float4 v = *(const float4*)&Qp[(size_t)(rowoff + qbase + r) * Dn + h * DKn + d4];
        float sc = L2E * 0.125f;
        *(uint4*)&sm[r * KST2 + d4] =
            make_uint4(f2tf(v.x * sc), f2tf(v.y * sc), f2tf(v.z * sc), f2tf(v.w * sc));
    }
    __syncthreads();

    unsigned qreg[8][4];                      // Q a-fragments: 32 regs
    #pragma unroll
    for (int oct = 0; oct < 8; oct++) {
        int kk = oct * 8 + 2 * t;
        uint2 alo = *(const uint2*)&sm[(wq + g) * KST2 + kk];
        uint2 ahi = *(const uint2*)&sm[(wq + g + 8) * KST2 + kk];
        qreg[oct][0] = alo.x; qreg[oct][1] = ahi.x;
        qreg[oct][2] = alo.y; qreg[oct][3] = ahi.y;
    }
    __syncthreads();                           // staging free; KV pipeline may overwrite

    float o[8][4];
    #pragma unroll
    for (int vt = 0; vt < 8; vt++)
        #pragma unroll
        for (int j = 0; j < 4; j++) o[vt][j] = 0.0f;
    float m0 = -1e30f, m1 = -1e30f, l0 = 0.0f, l1 = 0.0f;

    int rg0 = qbase + wq + g, rg1 = rg0 + 8;
    int jmax = 2 * qt + 1;                    // kv tiles of 32

    ISSUE_KV(0, 0);

    for (int jt = 0; jt <= jmax; jt++) {
        int cur = jt & 1;
        if (jt < jmax) {
            ISSUE_KV(cur ^ 1, (jt + 1) * 32);
            asm volatile("cp.async.wait_group 1;");
        } else {
            asm volatile("cp.async.wait_group 0;");
        }
        __syncthreads();

        unsigned* Ks = sm + cur * KVB;
        unsigned* Vs = Ks + KS2;
        const float* Bf = (const float*)(Vs + VS2);
        int kb = jt * 32;

        // ---- S = Q . K^T (k=64) ----
        float s[4][4];
        #pragma unroll
        for (int nt = 0; nt < 4; nt++)
            #pragma unroll
            for (int j = 0; j < 4; j++) s[nt][j] = 0.0f;

        #pragma unroll
        for (int oct = 0; oct < 8; oct++) {
            int kk = oct * 8 + 2 * t;
            #pragma unroll
            for (int nt = 0; nt < 4; nt++) {
                uint2 bb = *(const uint2*)&Ks[(nt * 8 + g) * KST2 + kk];
                mma8(s[nt], qreg[oct][0], qreg[oct][1], qreg[oct][2], qreg[oct][3],
                     bb.x, bb.y);
            }
        }

        // ---- add precomputed ASA bias (already * log2e) ----
        #pragma unroll
        for (int nt = 0; nt < 4; nt++) {
            float2 b0v = *(const float2*)&Bf[(wq + g) * BST2 + nt * 8 + 2 * t];
            float2 b1v = *(const float2*)&Bf[(wq + g + 8) * BST2 + nt * 8 + 2 * t];
            s[nt][0] += b0v.x; s[nt][1] += b0v.y;
            s[nt][2] += b1v.x; s[nt][3] += b1v.y;
        }

        // ---- causal mask ----
        if (kb + 31 > rg0) {
            #pragma unroll
            for (int nt = 0; nt < 4; nt++) {
                int c0 = kb + nt * 8 + 2 * t, c1 = c0 + 1;
                if (c0 > rg0) s[nt][0] = -1e30f;
                if (c1 > rg0) s[nt][1] = -1e30f;
                if (c0 > rg1) s[nt][2] = -1e30f;
                if (c1 > rg1) s[nt][3] = -1e30f;
            }
        }

        // ---- online softmax (base-2) ----
        float tm0 = -1e30f, tm1 = -1e30f;
        #pragma unroll
        for (int nt = 0; nt < 4; nt++) {
            tm0 = fmaxf(tm0, fmaxf(s[nt][0], s[nt][1]));
            tm1 = fmaxf(tm1, fmaxf(s[nt][2], s[nt][3]));
        }
        tm0 = fmaxf(tm0, __shfl_xor_sync(0xffffffffu, tm0, 1));
        tm0 = fmaxf(tm0, __shfl_xor_sync(0xffffffffu, tm0, 2));
        tm1 = fmaxf(tm1, __shfl_xor_sync(0xffffffffu, tm1, 1));
        tm1 = fmaxf(tm1, __shfl_xor_sync(0xffffffffu, tm1, 2));
        float mn0 = fmaxf(m0, tm0), mn1 = fmaxf(m1, tm1);
        float cr0 = ex2(m0 - mn0), cr1 = ex2(m1 - mn1);
        float rs0 = 0.0f, rs1 = 0.0f;
        #pragma unroll
        for (int nt = 0; nt < 4; nt++) {
            s[nt][0] = ex2(s[nt][0] - mn0);
            s[nt][1] = ex2(s[nt][1] - mn0);
            s[nt][2] = ex2(s[nt][2] - mn1);
            s[nt][3] = ex2(s[nt][3] - mn1);
            rs0 += s[nt][0] + s[nt][1];
            rs1 += s[nt][2] + s[nt][3];
        }
        rs0 += __shfl_xor_sync(0xffffffffu, rs0, 1);
        rs0 += __shfl_xor_sync(0xffffffffu, rs0, 2);
        rs1 += __shfl_xor_sync(0xffffffffu, rs1, 1);
        rs1 += __shfl_xor_sync(0xffffffffu, rs1, 2);
        l0 = l0 * cr0 + rs0; m0 = mn0;
        l1 = l1 * cr1 + rs1; m1 = mn1;
        #pragma unroll
        for (int vt = 0; vt < 8; vt++) {
            o[vt][0] *= cr0; o[vt][1] *= cr0;
            o[vt][2] *= cr1; o[vt][3] *= cr1;
        }

        // ---- P -> tf32, O += P . V ----
        #pragma unroll
        for (int nt = 0; nt < 4; nt++)
            #pragma unroll
            for (int j = 0; j < 4; j++)
                s[nt][j] = __uint_as_float(f2tf(s[nt][j]));

        #pragma unroll
        for (int oct = 0; oct < 4; oct++) {
            int kk = oct * 8 + 2 * t;
            unsigned pa0 = __float_as_uint(s[oct][0]);
            unsigned pa1 = __float_as_uint(s[oct][2]);
            unsigned pa2 = __float_as_uint(s[oct][1]);
            unsigned pa3 = __float_as_uint(s[oct][3]);
            #pragma unroll
            for (int vt = 0; vt < 8; vt++) {
                unsigned b0 = Vs[kk * VST2 + vt * 8 + g];
                unsigned b1 = Vs[(kk + 1) * VST2 + vt * 8 + g];
                mma8(o[vt], pa0, pa1, pa2, pa3, b0, b1);
            }
        }
        __syncthreads();
    }

    // ---- epilogue (rounded: feeds final tf32 GEMM) ----
    float inv0 = 1.0f / l0, inv1 = 1.0f / l1;
    int r0 = rowoff + rg0, r1 = rowoff + rg1;
    #pragma unroll
    for (int vt = 0; vt < 8; vt++) {
        int col = h * DKn + vt * 8 + 2 * t;
        *(uint2*)&O[(size_t)r0 * Dn + col] =
            make_uint2(f2tf(o[vt][0] * inv0), f2tf(o[vt][1] * inv0));
        *(uint2*)&O[(size_t)r1 * Dn + col] =
            make_uint2(f2tf(o[vt][2] * inv1), f2tf(o[vt][3] * inv1));
    }
}

// ---------------- launch ----------------
extern "C" void kernel_launch(void* const* d_in, const int* in_sizes, int n_in,
                              void* d_out, int out_size)
{
    const float* x    = (const float*)d_in[0];
    const float* feat = (const float*)d_in[1];
    const float* req  = (const float*)d_in[2];
    const float* Wq   = (const float*)d_in[3];
    const float* bq   = (const float*)d_in[4];
    const float* Wk   = (const float*)d_in[5];
    const float* bk   = (const float*)d_in[6];
    const float* Wv   = (const float*)d_in[7];
    const float* bv   = (const float*)d_in[8];
    const float* Wo   = (const float*)d_in[9];
    const float* bo   = (const float*)d_in[10];
    float* out = (float*)d_out;

    float *gQ, *gK, *gV, *gA, *gX, *gW, *gFn, *gRn, *gB;
    cudaGetSymbolAddress((void**)&gQ,  g_Q);
    cudaGetSymbolAddress((void**)&gK,  g_K);
    cudaGetSymbolAddress((void**)&gV,  g_V);
    cudaGetSymbolAddress((void**)&gA,  g_A);
    cudaGetSymbolAddress((void**)&gX,  g_X);
    cudaGetSymbolAddress((void**)&gW,  g_Wr);
    cudaGetSymbolAddress((void**)&gFn, g_Fn);
    cudaGetSymbolAddress((void**)&gRn, g_Rn);
    cudaGetSymbolAddress((void**)&gB,  g_Bias);
    const float* gWq = gW;
    const float* gWk = gW + Dn * Dn;
    const float* gWv = gW + 2 * Dn * Dn;
    const float* gWo = gW + 3 * Dn * Dn;

    cudaFuncSetAttribute(gemm_tf32,
                         cudaFuncAttributeMaxDynamicSharedMemorySize, GEMM_SMEM);
    cudaFuncSetAttribute(attn_tf32,
                         cudaFuncAttributeMaxDynamicSharedMemorySize, ATT_SMEM);
    cudaFuncSetAttribute(bias_gemm,
                         cudaFuncAttributeMaxDynamicSharedMemorySize, BIAS_SMEM);

    round_inputs<<<8192, 256>>>(x, Wq, Wk, Wv, Wo);
    l2norm_kernel<<<(2 * Bn * Sn) / 8, 256>>>(feat, req, gFn, gRn);
    bias_gemm<<<dim3(16, 16, 2), 256, BIAS_SMEM>>>(gRn, gFn, gB);

    gemm_tf32<<<dim3(8, 32, 3), 256, GEMM_SMEM>>>(
        gX, gWq, gWk, gWv, bq, bk, bv, gQ, gK, gV, 1);

    attn_tf32<<<dim3(32, Hn, Bn), 128, ATT_SMEM>>>(gQ, gK, gV, gB, gA);

    gemm_tf32<<<dim3(8, 32, 1), 256, GEMM_SMEM>>>(
        gA, gWo, gWo, gWo, bo, bo, bo, out, out, out, 0);
}